// round 16
// baseline (speedup 1.0000x reference)
#include <cuda_runtime.h>
#include <cuda_bf16.h>
#include <math.h>
#include <stdint.h>

// Problem constants
#define B_   32
#define T_   64
#define H_   256
#define N_   20000
#define G_   32
#define EPS_ 1e-5f

// ---------------- device scratch (static, no allocation) ----------------
__device__ int   d_lut[2 * N_];
__device__ float d_gsum[G_], d_gsq[G_], d_gscale[G_], d_gshift[G_];
__device__ float d_bns_sum[H_], d_bns_sq[H_], d_bns_scale[H_], d_bns_shift[H_];
__device__ float d_hbn_sum[3 * H_], d_hbn_sq[3 * H_], d_hbn_scale[3 * H_], d_hbn_shift[3 * H_];
__device__ float d_x0[B_ * T_ * 64];            // lstm input (B,T,64)
__device__ float d_bufB[B_ * T_ * H_];          // shared stack out (pre-BN)
__device__ float d_hbufB[3 * B_ * T_ * H_];     // head stacks out (chain-major, pre-BN)

// ---------------- helpers ----------------
__device__ __forceinline__ float fsig(float x) {
    return __fdividef(1.f, 1.f + __expf(-x));
}
__device__ __forceinline__ float ftanh(float x) {
    return __fdividef(2.f, 1.f + __expf(-2.f * x)) - 1.f;
}

#define FMA2(acc, a, b) \
    asm volatile("fma.rn.f32x2 %0, %1, %2, %0;" : "+l"(acc) : "l"(a), "l"(b))

__device__ __forceinline__ float pairsum(unsigned long long a) {
    float lo, hi;
    asm("mov.b64 {%0,%1}, %2;" : "=f"(lo), "=f"(hi) : "l"(a));
    return lo + hi;
}

// packed-pair dot: NP pairs (NP*2 floats) against register weights
template <int NP>
__device__ __forceinline__ float dotp(const unsigned long long* w2, const float* src) {
    const ulonglong2* v = reinterpret_cast<const ulonglong2*>(src);
    unsigned long long a0 = 0ull, a1 = 0ull, a2 = 0ull, a3 = 0ull;
#pragma unroll
    for (int i = 0; i < NP / 2; i += 2) {
        ulonglong2 hA = v[i];
        ulonglong2 hB = v[i + 1];
        FMA2(a0, w2[2 * i],     hA.x);
        FMA2(a1, w2[2 * i + 1], hA.y);
        FMA2(a2, w2[2 * i + 2], hB.x);
        FMA2(a3, w2[2 * i + 3], hB.y);
    }
    return (pairsum(a0) + pairsum(a1)) + (pairsum(a2) + pairsum(a3));
}

template <int NP>
__device__ __forceinline__ void load_w(unsigned long long* w2, const float* base) {
    const ulonglong2* p = reinterpret_cast<const ulonglong2*>(base);
#pragma unroll
    for (int i = 0; i < NP / 2; i++) {
        ulonglong2 v = p[i];
        w2[2 * i] = v.x;
        w2[2 * i + 1] = v.y;
    }
}

__device__ __forceinline__ void mbar_wait_par(unsigned addr, int parity) {
    asm volatile(
        "{\n\t.reg .pred P;\n\t"
        "LW%=:\n\t"
        "mbarrier.try_wait.parity.acquire.cluster.shared::cta.b64 P, [%0], %1, 0x989680;\n\t"
        "@P bra LD%=;\n\t"
        "bra LW%=;\n\t"
        "LD%=:\n\t}"
        :: "r"(addr), "r"((unsigned)parity) : "memory");
}

// ============================================================
// K0: zero stats + init LUT (graph replays -> must reset every launch)
// ============================================================
__global__ void init_kernel() {
    int i = blockIdx.x * blockDim.x + threadIdx.x;
    if (i < 2 * N_) d_lut[i] = 0x7fffffff;
    if (i < G_)  { d_gsum[i] = 0.f; d_gsq[i] = 0.f; }
    if (i < H_)  { d_bns_sum[i] = 0.f; d_bns_sq[i] = 0.f; }
    if (i < 3 * H_) { d_hbn_sum[i] = 0.f; d_hbn_sq[i] = 0.f; }
}

// ============================================================
// K1: GAT batchnorm stats (G=32 fastest dim -> feature == lane)
// ============================================================
__global__ void gat_stats_kernel(const float* __restrict__ g, int n_elems) {
    int lane = threadIdx.x & 31;
    int w = threadIdx.x >> 5;
    float s = 0.f, s2 = 0.f;
    for (long i = (long)blockIdx.x * blockDim.x + threadIdx.x; i < n_elems;
         i += (long)gridDim.x * blockDim.x) {
        float v = g[i];
        s += v; s2 += v * v;
    }
    __shared__ float ss[8][32], ss2[8][32];
    ss[w][lane] = s; ss2[w][lane] = s2;
    __syncthreads();
    if (threadIdx.x < 32) {
        float a = 0.f, b = 0.f;
#pragma unroll
        for (int ww = 0; ww < 8; ww++) { a += ss[ww][lane]; b += ss2[ww][lane]; }
        atomicAdd(&d_gsum[lane], a);
        atomicAdd(&d_gsq[lane], b);
    }
}

// ============================================================
// K2: LUT build — first occurrence (min index) per node value
// ============================================================
__global__ void lut_build_kernel(const int* __restrict__ node_ids) {
    int n = blockIdx.x * blockDim.x + threadIdx.x;
    if (n < N_) atomicMin(&d_lut[node_ids[n]], n);
}

// ============================================================
// K3: BN finalize
// ============================================================
__global__ void bn_finalize_kernel(const float* __restrict__ sum, const float* __restrict__ sq,
                                   const float* __restrict__ gamma, const float* __restrict__ beta,
                                   float* __restrict__ scale, float* __restrict__ shift,
                                   int n, float inv_cnt) {
    int i = blockIdx.x * blockDim.x + threadIdx.x;
    if (i < n) {
        float m = sum[i] * inv_cnt;
        float v = sq[i] * inv_cnt - m * m;
        float sc = gamma[i] * rsqrtf(v + EPS_);
        scale[i] = sc;
        shift[i] = beta[i] - m * sc;
    }
}

// ============================================================
// K4: build lstm input (B,T,64) = [data_feats | matched gat_norm]
// ============================================================
__global__ void build_x0_kernel(const float* __restrict__ feats,
                                const float* __restrict__ gat,
                                const int* __restrict__ row_ids) {
    int bt = blockIdx.x;
    int t = threadIdx.x;
    if (t < 32) {
        d_x0[bt * 64 + t] = feats[bt * 32 + t];
    } else {
        int gI = t - 32;
        int v = row_ids[bt];
        int n = d_lut[v];
        float val = 0.f;
        if (n != 0x7fffffff) {
            int b = bt >> 6;
            val = gat[((long)b * N_ + n) * G_ + gI] * d_gscale[gI] + d_gshift[gI];
        }
        d_x0[bt * 64 + 32 + gI] = val;
    }
}

// ============================================================
// recurrence pass (64 steps) — shared across both fused layers.
// hbuf: double-buffered 2x256. mbar: count=256 (8 CTAs x 32 lanes).
// ============================================================
template <bool ARCHIVE, bool STORE>
__device__ __forceinline__ void recur_pass(
    const unsigned long long* w2, float* hbuf, float* gp, const float* XP, float* X1,
    float* ob, unsigned mb_a, int& pcnt, int tid, int half, int helem)
{
    float creg = 0.f;
    for (int s = 0; s < T_; s++, pcnt++) {
        const int rb = s & 1;
        gp[tid] = dotp<64>(w2, hbuf + rb * 256 + half * 128);
        __syncthreads();
        if (tid < 32) {
            int xo = s * 128 + tid;
            float iv = XP[xo]      + gp[tid]       + gp[128 + tid];
            float fv = XP[xo + 32] + gp[32 + tid]  + gp[160 + tid];
            float gv = XP[xo + 64] + gp[64 + tid]  + gp[192 + tid];
            float ov = XP[xo + 96] + gp[96 + tid]  + gp[224 + tid];
            float ig = fsig(iv), fg = fsig(fv), og = fsig(ov);
            float gg = ftanh(gv);
            creg = fg * creg + ig * gg;
            float hn = og * ftanh(creg);
            if (STORE) ob[s * H_ + helem] = hn;
            unsigned laddr = (unsigned)__cvta_generic_to_shared(hbuf + (rb ^ 1) * 256 + helem);
#pragma unroll
            for (unsigned r = 0; r < 8; r++) {
                unsigned ra;
                asm volatile("mapa.shared::cluster.u32 %0, %1, %2;" : "=r"(ra) : "r"(laddr), "r"(r));
                asm volatile("st.shared::cluster.f32 [%0], %1;" :: "r"(ra), "f"(hn) : "memory");
            }
#pragma unroll
            for (unsigned r = 0; r < 8; r++) {
                unsigned rm;
                asm volatile("mapa.shared::cluster.u32 %0, %1, %2;" : "=r"(rm) : "r"(mb_a), "r"(r));
                asm volatile("mbarrier.arrive.release.cluster.shared::cluster.b64 _, [%0];"
                             :: "r"(rm) : "memory");
            }
        }
        mbar_wait_par(mb_a, pcnt & 1);
        if (ARCHIVE) X1[s * 256 + tid] = hbuf[(rb ^ 1) * 256 + tid];
    }
}

// ============================================================
// K5: fused 2-layer cluster LSTM.
// 8-CTA cluster per (head,batch) chain. CTA rank k owns h[32k,32k+32)
// = gate rows {q*256+32k+j}. 256 threads: lr=t&127 local row, half=t>>7
// input slice. Weights live in 64 packed-u64 regs per thread (f32x2 FMA).
// Layer0: input from gmem (opt. BN fold) -> h history archived to smem.
// Layer1: input = archived history -> output to gmem.
// Per-step cross-CTA h exchange: st.shared::cluster + mbarrier (no
// barrier.cluster on the hot path).
// ============================================================
template <int IN0>
__global__ void __launch_bounds__(256, 1) __cluster_dims__(8, 1, 1)
lstm2_kernel(const float* __restrict__ x, long x_head_stride, int apply_in_bn,
             const float* __restrict__ Wih0, const float* __restrict__ Whh0,
             const float* __restrict__ b0,
             const float* __restrict__ Wih1, const float* __restrict__ Whh1,
             const float* __restrict__ b1,
             long w_head_stride, long b_head_stride,
             float* __restrict__ out)
{
    extern __shared__ float sm[];
    unsigned long long* mb = reinterpret_cast<unsigned long long*>(sm);   // 8B
    float* gp   = sm + 4;                 // 256
    float* hbuf = sm + 260;               // 512 (2 x 256)
    float* X0   = sm + 772;               // T_*IN0
    float* XP   = X0 + T_ * IN0;          // 16384 (2 halves; combined into first 8192)
    float* X1   = XP + 16384;             // 16384 (L0 h history = L1 input)

    const int tid  = threadIdx.x;
    const int half = tid >> 7;
    const int lr   = tid & 127;
    const int rank = blockIdx.x & 7;
    const int chain = blockIdx.x >> 3;
    const int head = chain >> 5;
    const int b    = chain & 31;
    const int q = lr >> 5;
    const int j = lr & 31;
    const int grow  = q * 256 + rank * 32 + j;
    const int helem = rank * 32 + j;

    const float* xb = x + head * x_head_stride + (long)b * T_ * IN0;
    float* ob = out + (long)chain * (T_ * H_);
    unsigned mb_a = (unsigned)__cvta_generic_to_shared(mb);

    if (tid == 0) {
        asm volatile("mbarrier.init.shared.b64 [%0], %1;" :: "r"(mb_a), "r"(256) : "memory");
    }
    for (int i = tid; i < 512; i += 256) hbuf[i] = 0.f;

    if (apply_in_bn) {
        for (int i = tid; i < T_ * IN0; i += 256) {
            int f = i & (IN0 - 1);
            X0[i] = xb[i] * d_bns_scale[f] + d_bns_shift[f];
        }
    } else {
        for (int i = tid; i < T_ * IN0; i += 256) X0[i] = xb[i];
    }
    __syncthreads();
    // one-time cluster barrier: mbarrier init visible to peers before any arrive
    asm volatile("barrier.cluster.arrive.aligned;" ::: "memory");
    asm volatile("barrier.cluster.wait.aligned;" ::: "memory");

    int pcnt = 0;
    unsigned long long w2[64];

    // ================= layer 0 =================
    load_w<IN0 / 4>(w2, Wih0 + head * w_head_stride + (long)grow * IN0 + half * (IN0 / 2));
    {
        const float bias_v = (half == 0) ? (b0 + head * b_head_stride)[grow] : 0.f;
        for (int s = 0; s < T_; s++)
            XP[half * 8192 + s * 128 + lr] =
                dotp<IN0 / 4>(w2, X0 + s * IN0 + half * (IN0 / 2)) + bias_v;
    }
    __syncthreads();
    for (int i = tid; i < 8192; i += 256) XP[i] += XP[8192 + i];
    load_w<64>(w2, Whh0 + head * w_head_stride + (long)grow * 256 + half * 128);
    __syncthreads();

    recur_pass<true, false>(w2, hbuf, gp, XP, X1, ob, mb_a, pcnt, tid, half, helem);

    // reset h read-buffer (buffer 0) for layer 1
    hbuf[tid] = 0.f;

    // ================= layer 1 (IN = 256 from archived history) =================
    load_w<64>(w2, Wih1 + head * w_head_stride + (long)grow * 256 + half * 128);
    __syncthreads();          // covers archive writes + hbuf reset
    {
        const float bias_v = (half == 0) ? (b1 + head * b_head_stride)[grow] : 0.f;
        for (int s = 0; s < T_; s++)
            XP[half * 8192 + s * 128 + lr] =
                dotp<64>(w2, X1 + s * 256 + half * 128) + bias_v;
    }
    __syncthreads();
    for (int i = tid; i < 8192; i += 256) XP[i] += XP[8192 + i];
    load_w<64>(w2, Whh1 + head * w_head_stride + (long)grow * 256 + half * 128);
    __syncthreads();

    recur_pass<false, true>(w2, hbuf, gp, XP, X1, ob, mb_a, pcnt, tid, half, helem);
}

// ============================================================
// K6: per-feature stats over (B*T) rows; gridDim.y = heads
// ============================================================
__global__ void feat_stats_kernel(const float* __restrict__ x,
                                  float* __restrict__ sums, float* __restrict__ sqs,
                                  long head_stride) {
    int f = threadIdx.x;
    int head = blockIdx.y;
    const float* xb = x + head * head_stride;
    float s = 0.f, s2 = 0.f;
    for (int r = blockIdx.x; r < B_ * T_; r += gridDim.x) {
        float v = xb[(long)r * H_ + f];
        s += v; s2 += v * v;
    }
    atomicAdd(&sums[head * H_ + f], s);
    atomicAdd(&sqs[head * H_ + f], s2);
}

// ============================================================
// K7: final — BN(last step) + FCs + softmax
// ============================================================
__global__ void final_kernel(const float* __restrict__ hb,
                             const float* __restrict__ actW, const float* __restrict__ actB,
                             const float* __restrict__ tW, const float* __restrict__ tB,
                             const float* __restrict__ trW, const float* __restrict__ trB,
                             float* __restrict__ out) {
    int b = blockIdx.x;
    int t = threadIdx.x;
    __shared__ float l0[256], l1[256], l2[256];
    __shared__ float logits[32];

    l0[t] = hb[(((long)(0 * 32 + b)) * T_ + 63) * H_ + t] * d_hbn_scale[t]       + d_hbn_shift[t];
    l1[t] = hb[(((long)(1 * 32 + b)) * T_ + 63) * H_ + t] * d_hbn_scale[256 + t] + d_hbn_shift[256 + t];
    l2[t] = hb[(((long)(2 * 32 + b)) * T_ + 63) * H_ + t] * d_hbn_scale[512 + t] + d_hbn_shift[512 + t];
    __syncthreads();

    int w = t >> 5, lane = t & 31;
    if (w == 0) {
        float acc = actB[lane];
#pragma unroll 8
        for (int i = 0; i < 256; i++) acc = fmaf(l0[i], actW[lane * 256 + i], acc);
        logits[lane] = acc;
    } else if (w == 1) {
        float acc = 0.f;
        for (int i = lane; i < 256; i += 32) acc = fmaf(l1[i], tW[i], acc);
#pragma unroll
        for (int o = 16; o; o >>= 1) acc += __shfl_xor_sync(0xffffffffu, acc, o);
        if (lane == 0) out[1024 + b] = acc + tB[0];
    } else if (w == 2) {
        float acc = 0.f;
        for (int i = lane; i < 256; i += 32) acc = fmaf(l2[i], trW[i], acc);
#pragma unroll
        for (int o = 16; o; o >>= 1) acc += __shfl_xor_sync(0xffffffffu, acc, o);
        if (lane == 0) out[1056 + b] = acc + trB[0];
    }
    __syncthreads();
    if (w == 0) {
        float v = logits[lane];
        float mx = v;
#pragma unroll
        for (int o = 16; o; o >>= 1) mx = fmaxf(mx, __shfl_xor_sync(0xffffffffu, mx, o));
        float e = expf(v - mx);
        float sden = e;
#pragma unroll
        for (int o = 16; o; o >>= 1) sden += __shfl_xor_sync(0xffffffffu, sden, o);
        out[b * 32 + lane] = e / sden;
    }
}

// ============================================================
// host launcher
// ============================================================
extern "C" void kernel_launch(void* const* d_in, const int* in_sizes, int n_in,
                              void* d_out, int out_size) {
    (void)in_sizes; (void)n_in; (void)out_size;
    const float* data_feats = (const float*)d_in[0];
    const float* gat_output = (const float*)d_in[1];
    const int*   row_ids    = (const int*)d_in[2];
    const int*   node_ids   = (const int*)d_in[3];
    const float* sWih0 = (const float*)d_in[4];
    const float* sWhh0 = (const float*)d_in[5];
    const float* sb0   = (const float*)d_in[6];
    const float* sWih1 = (const float*)d_in[7];
    const float* sWhh1 = (const float*)d_in[8];
    const float* sb1   = (const float*)d_in[9];
    const float* hWih  = (const float*)d_in[10];
    const float* hWhh  = (const float*)d_in[11];
    const float* hbv   = (const float*)d_in[12];
    const float* bn_gnn_g = (const float*)d_in[13];
    const float* bn_gnn_b = (const float*)d_in[14];
    const float* bn_sh_g  = (const float*)d_in[15];
    const float* bn_sh_b  = (const float*)d_in[16];
    const float* hbn_g    = (const float*)d_in[17];
    const float* hbn_b    = (const float*)d_in[18];
    const float* actW = (const float*)d_in[19];
    const float* actB = (const float*)d_in[20];
    const float* tW   = (const float*)d_in[21];
    const float* tB   = (const float*)d_in[22];
    const float* trW  = (const float*)d_in[23];
    const float* trB  = (const float*)d_in[24];
    float* out = (float*)d_out;

    void* p;
    cudaGetSymbolAddress(&p, d_x0);        float* x0p  = (float*)p;
    cudaGetSymbolAddress(&p, d_bufB);      float* bufB = (float*)p;
    cudaGetSymbolAddress(&p, d_hbufB);     float* hbB  = (float*)p;
    cudaGetSymbolAddress(&p, d_gsum);      float* gsum = (float*)p;
    cudaGetSymbolAddress(&p, d_gsq);       float* gsq  = (float*)p;
    cudaGetSymbolAddress(&p, d_gscale);    float* gsc  = (float*)p;
    cudaGetSymbolAddress(&p, d_gshift);    float* gsh  = (float*)p;
    cudaGetSymbolAddress(&p, d_bns_sum);   float* bsum = (float*)p;
    cudaGetSymbolAddress(&p, d_bns_sq);    float* bsq  = (float*)p;
    cudaGetSymbolAddress(&p, d_bns_scale); float* bsc  = (float*)p;
    cudaGetSymbolAddress(&p, d_bns_shift); float* bsh  = (float*)p;
    cudaGetSymbolAddress(&p, d_hbn_sum);   float* hsum = (float*)p;
    cudaGetSymbolAddress(&p, d_hbn_sq);    float* hsq  = (float*)p;
    cudaGetSymbolAddress(&p, d_hbn_scale); float* hsc  = (float*)p;
    cudaGetSymbolAddress(&p, d_hbn_shift); float* hsh  = (float*)p;

    const int SMA = (772 + T_ * 64  + 16384 + 16384) * 4;   // 150544 B
    const int SMB = (772 + T_ * 256 + 16384 + 16384) * 4;   // 199696 B
    cudaFuncSetAttribute((const void*)lstm2_kernel<64>,
                         cudaFuncAttributeMaxDynamicSharedMemorySize, SMA);
    cudaFuncSetAttribute((const void*)lstm2_kernel<256>,
                         cudaFuncAttributeMaxDynamicSharedMemorySize, SMB);

    init_kernel<<<(2 * N_ + 255) / 256, 256>>>();
    gat_stats_kernel<<<1024, 256>>>(gat_output, B_ * N_ * G_);
    lut_build_kernel<<<(N_ + 255) / 256, 256>>>(node_ids);
    bn_finalize_kernel<<<1, 32>>>(gsum, gsq, bn_gnn_g, bn_gnn_b, gsc, gsh,
                                  G_, 1.f / (float)(B_ * N_));
    build_x0_kernel<<<B_ * T_, 64>>>(data_feats, gat_output, row_ids);

    // shared stack: 32 chains x 8 CTAs, both layers fused
    lstm2_kernel<64><<<B_ * 8, 256, SMA>>>(
        x0p, 0L, 0, sWih0, sWhh0, sb0, sWih1, sWhh1, sb1, 0L, 0L, bufB);

    feat_stats_kernel<<<dim3(64, 1), 256>>>(bufB, bsum, bsq, 0L);
    bn_finalize_kernel<<<1, 256>>>(bsum, bsq, bn_sh_g, bn_sh_b, bsc, bsh,
                                   H_, 1.f / (float)(B_ * T_));

    // head stacks: 96 chains x 8 CTAs, both layers fused; per-head stride 2*1024*256
    const long WHS = 2L * 1024 * 256;
    lstm2_kernel<256><<<3 * B_ * 8, 256, SMB>>>(
        bufB, 0L, 1,
        hWih, hWhh, hbv,
        hWih + 1024L * 256, hWhh + 1024L * 256, hbv + 1024,
        WHS, 2048L, hbB);

    feat_stats_kernel<<<dim3(64, 3), 256>>>(hbB, hsum, hsq, (long)B_ * T_ * H_);
    bn_finalize_kernel<<<3, 256>>>(hsum, hsq, hbn_g, hbn_b, hsc, hsh,
                                   3 * H_, 1.f / (float)(B_ * T_));

    final_kernel<<<B_, 256>>>(hbB, actW, actB, tW, tB, trW, trB, out);
}

// round 17
// speedup vs baseline: 2.4779x; 2.4779x over previous
#include <cuda_runtime.h>
#include <math.h>
#include <stdint.h>

#define B_   32
#define T_   64
#define H_   256
#define N_   20000
#define G_   32
#define EPS_ 1e-5f
#define SC_  4

// ---------------- device scratch ----------------
__device__ int   d_lut[2 * N_];
__device__ float d_gsum[G_], d_gsq[G_], d_gscale[G_], d_gshift[G_];
__device__ float d_bns_sum[H_], d_bns_sq[H_], d_bns_scale[H_], d_bns_shift[H_];
__device__ float d_hbn_sum[3 * H_], d_hbn_sq[3 * H_], d_hbn_scale[3 * H_], d_hbn_shift[3 * H_];
__device__ float d_x0[B_ * T_ * 64];
__device__ float d_bufB[B_ * T_ * H_];
__device__ float d_hbufB[3 * B_ * T_ * H_];
__device__ float d_xp[96 * 8 * T_ * 256];      // per-CTA xp scratch (max: head launch)
__device__ float d_hist[3 * B_ * T_ * H_];     // L0 hidden history (L1 input)

// ---------------- helpers ----------------
__device__ __forceinline__ float fsig(float x)  { return __fdividef(1.f, 1.f + __expf(-x)); }
__device__ __forceinline__ float ftanh(float x) { return __fdividef(2.f, 1.f + __expf(-2.f * x)) - 1.f; }

#define FMA2(acc, a, b) \
    asm volatile("fma.rn.f32x2 %0, %1, %2, %0;" : "+l"(acc) : "l"(a), "l"(b))

__device__ __forceinline__ float pairsum(unsigned long long a) {
    float lo, hi;
    asm("mov.b64 {%0,%1}, %2;" : "=f"(lo), "=f"(hi) : "l"(a));
    return lo + hi;
}
__device__ __forceinline__ unsigned smem_u32(const void* p) {
    return (unsigned)__cvta_generic_to_shared(p);
}
__device__ __forceinline__ void cluster_bar() {
    asm volatile("barrier.cluster.arrive.aligned;" ::: "memory");
    asm volatile("barrier.cluster.wait.aligned;"   ::: "memory");
}

template <int NP>
__device__ __forceinline__ float dotp(const unsigned long long* w2, const float* src) {
    const ulonglong2* v = reinterpret_cast<const ulonglong2*>(src);
    unsigned long long a0 = 0ull, a1 = 0ull, a2 = 0ull, a3 = 0ull;
#pragma unroll
    for (int i = 0; i < NP / 2; i += 2) {
        ulonglong2 hA = v[i];
        ulonglong2 hB = v[i + 1];
        FMA2(a0, w2[2 * i],     hA.x);
        FMA2(a1, w2[2 * i + 1], hA.y);
        FMA2(a2, w2[2 * i + 2], hB.x);
        FMA2(a3, w2[2 * i + 3], hB.y);
    }
    return (pairsum(a0) + pairsum(a1)) + (pairsum(a2) + pairsum(a3));
}

// ============ small kernels ============
__global__ void init_kernel() {
    int i = blockIdx.x * blockDim.x + threadIdx.x;
    if (i < 2 * N_) d_lut[i] = 0x7fffffff;
    if (i < G_)  { d_gsum[i] = 0.f; d_gsq[i] = 0.f; }
    if (i < H_)  { d_bns_sum[i] = 0.f; d_bns_sq[i] = 0.f; }
    if (i < 3 * H_) { d_hbn_sum[i] = 0.f; d_hbn_sq[i] = 0.f; }
}

__global__ void gat_stats_kernel(const float* __restrict__ g, int n_elems) {
    int lane = threadIdx.x & 31, w = threadIdx.x >> 5;
    float s = 0.f, s2 = 0.f;
    for (long i = (long)blockIdx.x * blockDim.x + threadIdx.x; i < n_elems;
         i += (long)gridDim.x * blockDim.x) {
        float v = g[i];
        s += v; s2 += v * v;
    }
    __shared__ float ss[8][32], ss2[8][32];
    ss[w][lane] = s; ss2[w][lane] = s2;
    __syncthreads();
    if (threadIdx.x < 32) {
        float a = 0.f, b = 0.f;
#pragma unroll
        for (int ww = 0; ww < 8; ww++) { a += ss[ww][lane]; b += ss2[ww][lane]; }
        atomicAdd(&d_gsum[lane], a);
        atomicAdd(&d_gsq[lane], b);
    }
}

__global__ void lut_build_kernel(const int* __restrict__ node_ids) {
    int n = blockIdx.x * blockDim.x + threadIdx.x;
    if (n < N_) atomicMin(&d_lut[node_ids[n]], n);
}

__global__ void bn_finalize_kernel(const float* __restrict__ sum, const float* __restrict__ sq,
                                   const float* __restrict__ gamma, const float* __restrict__ beta,
                                   float* __restrict__ scale, float* __restrict__ shift,
                                   int n, float inv_cnt) {
    int i = blockIdx.x * blockDim.x + threadIdx.x;
    if (i < n) {
        float m = sum[i] * inv_cnt;
        float v = sq[i] * inv_cnt - m * m;
        float sc = gamma[i] * rsqrtf(v + EPS_);
        scale[i] = sc;
        shift[i] = beta[i] - m * sc;
    }
}

__global__ void build_x0_kernel(const float* __restrict__ feats,
                                const float* __restrict__ gat,
                                const int* __restrict__ row_ids) {
    int bt = blockIdx.x, t = threadIdx.x;
    if (t < 32) {
        d_x0[bt * 64 + t] = feats[bt * 32 + t];
    } else {
        int gI = t - 32;
        int n = d_lut[row_ids[bt]];
        float val = 0.f;
        if (n != 0x7fffffff) {
            int b = bt >> 6;
            val = gat[((long)b * N_ + n) * G_ + gI] * d_gscale[gI] + d_gshift[gI];
        }
        d_x0[bt * 64 + 32 + gI] = val;
    }
}

// ============================================================
// one LSTM layer inside an 8-CTA cluster, NB batches in lockstep.
// thread t: half=t>>7 (input slice of 128), lr=t&127 (local gate row);
// CTA rank owns gate rows {q*256 + rank*32 + j} and h[rank*32, +32).
// Phase 1: xp = Wih-half @ x staged from smem chunks -> gmem scratch.
// Phase 2: per step NB broadcast-LDS dots, NB epilogue warps do
// activations, store h to dst + broadcast to all 8 CTAs' hbuf via
// DSMEM, then barrier.cluster.
// ============================================================
template <int IN, int NB>
__device__ __forceinline__ void run_layer(
    float* stage, float* gp, float* hbuf,
    const float* __restrict__ src, long src_bstride,
    const float* __restrict__ Wih, const float* __restrict__ Whh,
    const float* __restrict__ bias, bool fold,
    float* __restrict__ myxp, float* __restrict__ dst,
    int tid, int half, int grow, bool epi, int eb, int helem, int lane)
{
    constexpr int NPW = IN / 4;
    unsigned long long w2[64];

    // Wih half-slice (optionally folding input-BN)
    float biasv = (half == 0) ? bias[grow] : 0.f;
    {
        const float* wb = Wih + (long)grow * IN + half * (IN / 2);
        if (fold) {
            const float* scb = d_bns_scale + half * (IN / 2);
            const float* shb = d_bns_shift + half * (IN / 2);
            float fs = 0.f;
#pragma unroll
            for (int i = 0; i < NPW; i++) {
                float2 wv  = reinterpret_cast<const float2*>(wb)[i];
                float2 scv = reinterpret_cast<const float2*>(scb)[i];
                float2 shv = reinterpret_cast<const float2*>(shb)[i];
                fs += wv.x * shv.x + wv.y * shv.y;
                wv.x *= scv.x; wv.y *= scv.y;
                asm("mov.b64 %0, {%1,%2};" : "=l"(w2[i]) : "f"(wv.x), "f"(wv.y));
            }
            biasv += fs;
        } else {
#pragma unroll
            for (int i = 0; i < NPW / 2; i++) {
                ulonglong2 v = reinterpret_cast<const ulonglong2*>(wb)[i];
                w2[2 * i] = v.x; w2[2 * i + 1] = v.y;
            }
        }
    }

    // phase 1: xp
    for (int s0 = 0; s0 < T_; s0 += SC_) {
        for (int i4 = tid * 4; i4 < NB * SC_ * IN; i4 += 1024) {
            int b = i4 / (SC_ * IN);
            int r = i4 - b * (SC_ * IN);
            *reinterpret_cast<float4*>(stage + i4) =
                *reinterpret_cast<const float4*>(src + (long)b * src_bstride + s0 * IN + r);
        }
        __syncthreads();
#pragma unroll 1
        for (int b = 0; b < NB; b++)
#pragma unroll 1
            for (int sl = 0; sl < SC_; sl++)
                myxp[(long)b * (T_ * 256) + (s0 + sl) * 256 + tid] =
                    dotp<NPW>(w2, stage + (b * SC_ + sl) * IN + half * (IN / 2)) + biasv;
        __syncthreads();
    }

    // Whh half-slice
    {
        const float* wb = Whh + (long)grow * 256 + half * 128;
#pragma unroll
        for (int i = 0; i < 32; i++) {
            ulonglong2 v = reinterpret_cast<const ulonglong2*>(wb)[i];
            w2[2 * i] = v.x; w2[2 * i + 1] = v.y;
        }
    }
    for (int i = tid; i < 2 * NB * 256; i += 256) hbuf[i] = 0.f;
    __syncthreads();
    cluster_bar();   // hbuf reset visible before peer DSMEM writes

    // phase 2: recurrence
    float creg = 0.f;
    const float* xpb = myxp + (long)eb * (T_ * 256);
    for (int s = 0; s < T_; s++) {
        float xq0, xq1, xq2, xq3, xq4, xq5, xq6, xq7;
        if (epi) {
            const float* xr = xpb + s * 256 + lane;
            xq0 = xr[0];   xq1 = xr[32];  xq2 = xr[64];  xq3 = xr[96];
            xq4 = xr[128]; xq5 = xr[160]; xq6 = xr[192]; xq7 = xr[224];
        }
        const int rb = s & 1;
        const float* hb = hbuf + rb * NB * 256 + half * 128;
#pragma unroll 1
        for (int b = 0; b < NB; b++)
            gp[b * 256 + tid] = dotp<64>(w2, hb + b * 256);
        __syncthreads();
        if (epi) {
            const float* g = gp + eb * 256 + lane;
            float g0 = xq0 + xq4 + g[0]  + g[128];
            float g1 = xq1 + xq5 + g[32] + g[160];
            float g2 = xq2 + xq6 + g[64] + g[192];
            float g3 = xq3 + xq7 + g[96] + g[224];
            float ig = fsig(g0), fg = fsig(g1), og = fsig(g3);
            float gg = ftanh(g2);
            creg = fg * creg + ig * gg;
            float hn = og * ftanh(creg);
            dst[(long)eb * (T_ * 256) + s * 256 + helem] = hn;
            unsigned la = smem_u32(hbuf + (rb ^ 1) * NB * 256 + eb * 256 + helem);
#pragma unroll
            for (unsigned r = 0; r < 8; r++) {
                unsigned ra;
                asm volatile("mapa.shared::cluster.u32 %0, %1, %2;" : "=r"(ra) : "r"(la), "r"(r));
                asm volatile("st.shared::cluster.f32 [%0], %1;" :: "r"(ra), "f"(hn) : "memory");
            }
        }
        cluster_bar();
    }
}

// ============================================================
// fused 2-layer LSTM stack, NB batches per 8-CTA cluster
// ============================================================
template <int IN0, int NB>
__global__ void __launch_bounds__(256, 1) __cluster_dims__(8, 1, 1)
lstm2_kernel(const float* __restrict__ x, long x_head_stride, int fold0,
             const float* __restrict__ Wih0, const float* __restrict__ Whh0,
             const float* __restrict__ b0,
             const float* __restrict__ Wih1, const float* __restrict__ Whh1,
             const float* __restrict__ b1,
             long whs, long bhs, float* __restrict__ out, int CPH)
{
    extern __shared__ float sm[];
    float* stage = sm;                           // NB*SC_*256
    float* gp    = stage + NB * SC_ * 256;       // NB*256
    float* hbuf  = gp + NB * 256;                // 2*NB*256

    const int tid  = threadIdx.x;
    const int half = tid >> 7;
    const int lr   = tid & 127;
    const int rank = blockIdx.x & 7;
    const int cid  = blockIdx.x >> 3;
    const int head = cid / CPH;
    const int bg   = cid - head * CPH;
    const int q = lr >> 5, j = lr & 31;
    const int grow = q * 256 + rank * 32 + j;
    const int wid = tid >> 5, lane = tid & 31;
    const bool epi = wid < NB;
    const int eb = wid;
    const int helem = rank * 32 + lane;
    const int batch0 = bg * NB;

    float* myxp = d_xp + (long)blockIdx.x * (NB * T_ * 256);
    float* hist = d_hist + (long)(cid * NB) * (T_ * 256);

    run_layer<IN0, NB>(stage, gp, hbuf,
        x + head * x_head_stride + (long)batch0 * T_ * IN0, (long)T_ * IN0,
        Wih0 + head * whs, Whh0 + head * whs, b0 + head * bhs, fold0 != 0,
        myxp, hist, tid, half, grow, epi, eb, helem, lane);

    run_layer<256, NB>(stage, gp, hbuf,
        hist, (long)T_ * 256,
        Wih1 + head * whs, Whh1 + head * whs, b1 + head * bhs, false,
        myxp, out + (long)(head * 32 + batch0) * T_ * 256,
        tid, half, grow, epi, eb, helem, lane);
}

// ============ stats + final ============
__global__ void feat_stats_kernel(const float* __restrict__ x,
                                  float* __restrict__ sums, float* __restrict__ sqs,
                                  long head_stride) {
    int f = threadIdx.x;
    int head = blockIdx.y;
    const float* xb = x + head * head_stride;
    float s = 0.f, s2 = 0.f;
    for (int r = blockIdx.x; r < B_ * T_; r += gridDim.x) {
        float v = xb[(long)r * H_ + f];
        s += v; s2 += v * v;
    }
    atomicAdd(&sums[head * H_ + f], s);
    atomicAdd(&sqs[head * H_ + f], s2);
}

__global__ void final_kernel(const float* __restrict__ hb,
                             const float* __restrict__ actW, const float* __restrict__ actB,
                             const float* __restrict__ tW, const float* __restrict__ tB,
                             const float* __restrict__ trW, const float* __restrict__ trB,
                             float* __restrict__ out) {
    int b = blockIdx.x, t = threadIdx.x;
    __shared__ float l0[256], l1[256], l2[256];
    __shared__ float logits[32];

    l0[t] = hb[(((long)(0 * 32 + b)) * T_ + 63) * H_ + t] * d_hbn_scale[t]       + d_hbn_shift[t];
    l1[t] = hb[(((long)(1 * 32 + b)) * T_ + 63) * H_ + t] * d_hbn_scale[256 + t] + d_hbn_shift[256 + t];
    l2[t] = hb[(((long)(2 * 32 + b)) * T_ + 63) * H_ + t] * d_hbn_scale[512 + t] + d_hbn_shift[512 + t];
    __syncthreads();

    int w = t >> 5, lane = t & 31;
    if (w == 0) {
        float acc = actB[lane];
#pragma unroll 8
        for (int i = 0; i < 256; i++) acc = fmaf(l0[i], actW[lane * 256 + i], acc);
        logits[lane] = acc;
    } else if (w == 1) {
        float acc = 0.f;
        for (int i = lane; i < 256; i += 32) acc = fmaf(l1[i], tW[i], acc);
#pragma unroll
        for (int o = 16; o; o >>= 1) acc += __shfl_xor_sync(0xffffffffu, acc, o);
        if (lane == 0) out[1024 + b] = acc + tB[0];
    } else if (w == 2) {
        float acc = 0.f;
        for (int i = lane; i < 256; i += 32) acc = fmaf(l2[i], trW[i], acc);
#pragma unroll
        for (int o = 16; o; o >>= 1) acc += __shfl_xor_sync(0xffffffffu, acc, o);
        if (lane == 0) out[1056 + b] = acc + trB[0];
    }
    __syncthreads();
    if (w == 0) {
        float v = logits[lane];
        float mx = v;
#pragma unroll
        for (int o = 16; o; o >>= 1) mx = fmaxf(mx, __shfl_xor_sync(0xffffffffu, mx, o));
        float e = expf(v - mx);
        float sden = e;
#pragma unroll
        for (int o = 16; o; o >>= 1) sden += __shfl_xor_sync(0xffffffffu, sden, o);
        out[b * 32 + lane] = e / sden;
    }
}

// ============================================================
extern "C" void kernel_launch(void* const* d_in, const int* in_sizes, int n_in,
                              void* d_out, int out_size) {
    (void)in_sizes; (void)n_in; (void)out_size;
    const float* data_feats = (const float*)d_in[0];
    const float* gat_output = (const float*)d_in[1];
    const int*   row_ids    = (const int*)d_in[2];
    const int*   node_ids   = (const int*)d_in[3];
    const float* sWih0 = (const float*)d_in[4];
    const float* sWhh0 = (const float*)d_in[5];
    const float* sb0   = (const float*)d_in[6];
    const float* sWih1 = (const float*)d_in[7];
    const float* sWhh1 = (const float*)d_in[8];
    const float* sb1   = (const float*)d_in[9];
    const float* hWih  = (const float*)d_in[10];
    const float* hWhh  = (const float*)d_in[11];
    const float* hbv   = (const float*)d_in[12];
    const float* bn_gnn_g = (const float*)d_in[13];
    const float* bn_gnn_b = (const float*)d_in[14];
    const float* bn_sh_g  = (const float*)d_in[15];
    const float* bn_sh_b  = (const float*)d_in[16];
    const float* hbn_g    = (const float*)d_in[17];
    const float* hbn_b    = (const float*)d_in[18];
    const float* actW = (const float*)d_in[19];
    const float* actB = (const float*)d_in[20];
    const float* tW   = (const float*)d_in[21];
    const float* tB   = (const float*)d_in[22];
    const float* trW  = (const float*)d_in[23];
    const float* trB  = (const float*)d_in[24];
    float* out = (float*)d_out;

    void* p;
    cudaGetSymbolAddress(&p, d_x0);        float* x0p  = (float*)p;
    cudaGetSymbolAddress(&p, d_bufB);      float* bufB = (float*)p;
    cudaGetSymbolAddress(&p, d_hbufB);     float* hbB  = (float*)p;
    cudaGetSymbolAddress(&p, d_gsum);      float* gsum = (float*)p;
    cudaGetSymbolAddress(&p, d_gsq);       float* gsq  = (float*)p;
    cudaGetSymbolAddress(&p, d_gscale);    float* gsc  = (float*)p;
    cudaGetSymbolAddress(&p, d_gshift);    float* gsh  = (float*)p;
    cudaGetSymbolAddress(&p, d_bns_sum);   float* bsum = (float*)p;
    cudaGetSymbolAddress(&p, d_bns_sq);    float* bsq  = (float*)p;
    cudaGetSymbolAddress(&p, d_bns_scale); float* bsc  = (float*)p;
    cudaGetSymbolAddress(&p, d_bns_shift); float* bsh  = (float*)p;
    cudaGetSymbolAddress(&p, d_hbn_sum);   float* hsum = (float*)p;
    cudaGetSymbolAddress(&p, d_hbn_sq);    float* hsq  = (float*)p;
    cudaGetSymbolAddress(&p, d_hbn_scale); float* hsc  = (float*)p;
    cudaGetSymbolAddress(&p, d_hbn_shift); float* hsh  = (float*)p;

    const int SMS = (2 * SC_ * 256 + 2 * 256 + 2 * 2 * 256) * 4;   // NB=2 : 14336 B
    const int SMH = (8 * SC_ * 256 + 8 * 256 + 2 * 8 * 256) * 4;   // NB=8 : 57344 B
    cudaFuncSetAttribute((const void*)lstm2_kernel<64, 2>,
                         cudaFuncAttributeMaxDynamicSharedMemorySize, SMS);
    cudaFuncSetAttribute((const void*)lstm2_kernel<256, 8>,
                         cudaFuncAttributeMaxDynamicSharedMemorySize, SMH);

    init_kernel<<<(2 * N_ + 255) / 256, 256>>>();
    gat_stats_kernel<<<1024, 256>>>(gat_output, B_ * N_ * G_);
    lut_build_kernel<<<(N_ + 255) / 256, 256>>>(node_ids);
    bn_finalize_kernel<<<1, 32>>>(gsum, gsq, bn_gnn_g, bn_gnn_b, gsc, gsh,
                                  G_, 1.f / (float)(B_ * N_));
    build_x0_kernel<<<B_ * T_, 64>>>(data_feats, gat_output, row_ids);

    // shared stack: 16 clusters x 8 CTAs, NB=2 (one wave)
    lstm2_kernel<64, 2><<<16 * 8, 256, SMS>>>(
        x0p, 0L, 0, sWih0, sWhh0, sb0, sWih1, sWhh1, sb1, 0L, 0L, bufB, 16);

    feat_stats_kernel<<<dim3(64, 1), 256>>>(bufB, bsum, bsq, 0L);
    bn_finalize_kernel<<<1, 256>>>(bsum, bsq, bn_sh_g, bn_sh_b, bsc, bsh,
                                   H_, 1.f / (float)(B_ * T_));

    // head stacks: 12 clusters x 8 CTAs, NB=8, 4 clusters/head (one wave)
    const long WHS = 2L * 1024 * 256;
    lstm2_kernel<256, 8><<<12 * 8, 256, SMH>>>(
        bufB, 0L, 1,
        hWih, hWhh, hbv,
        hWih + 1024L * 256, hWhh + 1024L * 256, hbv + 1024,
        WHS, 2048L, hbB, 4);

    feat_stats_kernel<<<dim3(64, 3), 256>>>(hbB, hsum, hsq, (long)B_ * T_ * H_);
    bn_finalize_kernel<<<3, 256>>>(hsum, hsq, hbn_g, hbn_b, hsc, hsh,
                                   3 * H_, 1.f / (float)(B_ * T_));

    final_kernel<<<B_, 256>>>(hbB, actW, actB, tW, tB, trW, trB, out);
}